// round 15
// baseline (speedup 1.0000x reference)
#include <cuda_runtime.h>

#define B  32
#define S  617
#define D  10000
#define L  100
#define C  26
#define W  313        // ceil(D/32) real words
#define WP 320        // padded word count

// ---------------- device globals (pads stay zero forever) ---------------------------------------
__device__ __align__(16) unsigned g_idp[S * WP];   // packed id signs    [s][w]
__device__ __align__(16) unsigned g_lvp[L * WP];   // packed level signs [l][w]

// ================= kernel 1: pack sign bits (measured-best MLP-8 float4 + shfl); zero out =======
#define NROWS (S + L)                        // 717
#define RPR   10                             // regions of 1024 floats per row
#define PREP_WARPS  (NROWS * RPR)            // 7170
#define PREP_BLOCKS ((PREP_WARPS + 7) / 8)   // 897

__global__ __launch_bounds__(256) void prep_kernel(const float* __restrict__ idw,
                                                   const float* __restrict__ lvw,
                                                   float* __restrict__ out) {
    // zero the output accumulators (B*C = 832 floats; harness poisons them each replay)
    if (blockIdx.x == 0) {
        for (int i = threadIdx.x; i < B * C; i += 256) out[i] = 0.0f;
    }

    const int lane = threadIdx.x & 31;
    const int gw   = blockIdx.x * 8 + (threadIdx.x >> 5);
    if (gw >= PREP_WARPS) return;

    const int r      = gw / RPR;
    const int region = gw - r * RPR;
    const float* src = (r < S) ? (idw + (size_t)r * D) : (lvw + (size_t)(r - S) * D);
    unsigned*    dst = (r < S) ? (g_idp + r * WP)       : (g_lvp + (r - S) * WP);

    const int qbase = region * 256;

    float4 v[8];
    #pragma unroll
    for (int k = 0; k < 8; k++) {
        int q = qbase + k * 32 + lane;
        if (q < D / 4) v[k] = *reinterpret_cast<const float4*>(src + 4 * q);
        else           v[k] = make_float4(0.f, 0.f, 0.f, 0.f);
    }

    unsigned nib[8];
    #pragma unroll
    for (int k = 0; k < 8; k++) {
        unsigned n = (v[k].x > 0.f ? 1u : 0u) | (v[k].y > 0.f ? 2u : 0u)
                   | (v[k].z > 0.f ? 4u : 0u) | (v[k].w > 0.f ? 8u : 0u);
        n |= __shfl_down_sync(0xffffffffu, n, 1) << 4;
        n |= __shfl_down_sync(0xffffffffu, n, 2) << 8;
        n |= __shfl_down_sync(0xffffffffu, n, 4) << 16;
        nib[k] = n;
    }

    if ((lane & 7) == 0) {
        const int g = lane >> 3;
        #pragma unroll
        for (int k = 0; k < 8; k++) {
            int w = region * 32 + 4 * k + g;
            if (w < W) dst[w] = nib[k];
        }
    }
}

// ---------------- 6-sample bitplane compressor (26 LOP3 per 6 samples) --------------------------
__device__ __forceinline__ void csa6(const unsigned xx[6], unsigned p[7]) {
    unsigned t01 = xx[0] ^ xx[1];
    unsigned l1  = t01 ^ xx[2];
    unsigned h1  = (xx[0] & xx[1]) | (xx[2] & t01);
    unsigned t34 = xx[3] ^ xx[4];
    unsigned l2  = t34 ^ xx[5];
    unsigned h2  = (xx[3] & xx[4]) | (xx[5] & t34);
    unsigned tl = l1 ^ l2;
    unsigned c0 = (l1 & l2) | (p[0] & tl);
    p[0] ^= tl;
    unsigned th  = h1 ^ h2;
    unsigned c1a = (h1 & h2) | (p[1] & th);
    unsigned s1  = p[1] ^ th;
    unsigned c1b = s1 & c0;
    p[1] = s1 ^ c0;
    unsigned tc = c1a ^ c1b;
    unsigned c2 = (c1a & c1b) | (p[2] & tc);
    p[2] ^= tc;
    unsigned t;
    t = p[3] & c2; p[3] ^= c2; c2 = t;
    t = p[4] & c2; p[4] ^= c2; c2 = t;
    t = p[5] & c2; p[5] ^= c2; c2 = t;
    p[6] ^= c2;
}

// ---------------- bit-sliced compare cnt < 309 (309 = 0b0100110101) -----------------------------
__device__ __forceinline__ unsigned cmp309(const unsigned A[10]) {
    unsigned lt = 0u, eq = 0xffffffffu;
    eq &= ~A[9];
    lt |= eq & ~A[8]; eq &= A[8];
    eq &= ~A[7];
    eq &= ~A[6];
    lt |= eq & ~A[5]; eq &= A[5];
    lt |= eq & ~A[4]; eq &= A[4];
    eq &= ~A[3];
    lt |= eq & ~A[2]; eq &= A[2];
    eq &= ~A[1];
    lt |= eq & ~A[0];
    return lt;
}

// ================= kernel 2: per-block enc slice + partial logits (no cross-block dep) ==========
// grid (B, 5): block = (batch b, 64-word group wg = 2048 d's). 512 threads = 16 sample warps.
// Phase A: bit-sliced disagreement count -> enc[64 words] in smem.
// Phase B: partial logits over this block's 2048 d's for all 26 classes -> atomicAdd(out[b][c]).
__global__ __launch_bounds__(512) void mainlogits_kernel(const float* __restrict__ x,
                                                         const float* __restrict__ cw,
                                                         float* __restrict__ out) {
    const int b    = blockIdx.x;
    const int wg   = blockIdx.y;            // 0..4
    const int tid  = threadIdx.x;
    const int lane = tid & 31;
    const int sg   = tid >> 5;              // 0..15 sample group
    const int w0   = wg * 64 + lane * 2;    // even global word index for phase A

    __shared__ __align__(16) unsigned pl[16 * 7 * 64];  // 28.7 KB
    __shared__ __align__(16) int      sidx[624];
    __shared__ __align__(16) unsigned s_enc[64];
    __shared__ float sp[16][C];                          // per-warp class partials

    // quantize x row b (rintf = half-even, matches jnp.round)
    for (int i = tid; i < S; i += 512) {
        int qv = (int)rintf(__ldg(&x[b * S + i]) * (float)(L - 1));
        sidx[i] = min(max(qv, 0), L - 1);
    }
    __syncthreads();

    // ----- phase A: each warp counts its ~39 samples over 64 words (uint2 per thread) -----
    const int s0 = sg * 39;                 // 15*39 + 32 = 617
    const int sn = (sg == 15) ? 32 : 39;

    unsigned pA[7] = {0,0,0,0,0,0,0};
    unsigned pB[7] = {0,0,0,0,0,0,0};

    const int full6 = sn / 6;               // 6 or 5
    for (int g = 0; g < full6; g++) {
        unsigned xa[6], xb[6];
        #pragma unroll
        for (int k = 0; k < 6; k++) {
            int s = s0 + g * 6 + k;
            uint2 a = *reinterpret_cast<const uint2*>(g_idp + s * WP + w0);
            uint2 l = *reinterpret_cast<const uint2*>(g_lvp + sidx[s] * WP + w0);
            xa[k] = a.x ^ l.x;
            xb[k] = a.y ^ l.y;
        }
        csa6(xa, pA);
        csa6(xb, pB);
    }
    for (int s = s0 + full6 * 6; s < s0 + sn; s++) {     // remainder: 3 or 2 samples
        uint2 a = *reinterpret_cast<const uint2*>(g_idp + s * WP + w0);
        uint2 l = *reinterpret_cast<const uint2*>(g_lvp + sidx[s] * WP + w0);
        unsigned cA = a.x ^ l.x, cB = a.y ^ l.y;
        #pragma unroll
        for (int k = 0; k < 7; k++) {
            unsigned t = pA[k] & cA; pA[k] ^= cA; cA = t;
            t = pB[k] & cB; pB[k] ^= cB; cB = t;
        }
    }

    #pragma unroll
    for (int k = 0; k < 7; k++) {
        uint2 v; v.x = pA[k]; v.y = pB[k];
        *reinterpret_cast<uint2*>(&pl[(sg * 7 + k) * 64 + lane * 2]) = v;
    }
    __syncthreads();

    // warps 0,1 merge the 16 groups (counts <= 617 < 1024, 10 bitplanes) and quantize
    if (tid < 64) {
        const int lw = tid;                 // local word 0..63
        unsigned A[10];
        #pragma unroll
        for (int k = 0; k < 10; k++) A[k] = 0u;
        #pragma unroll
        for (int g2 = 0; g2 < 16; g2++) {
            unsigned c = 0u;
            #pragma unroll
            for (int k = 0; k < 7; k++) {
                unsigned q = pl[(g2 * 7 + k) * 64 + lw];
                unsigned s2 = A[k] ^ q ^ c;
                c = (A[k] & q) | (c & (A[k] ^ q));
                A[k] = s2;
            }
            #pragma unroll
            for (int k = 7; k < 10; k++) { unsigned t = A[k] & c; A[k] ^= c; c = t; }
        }
        s_enc[lw] = cmp309(A);
    }
    __syncthreads();

    // ----- phase B: partial logits over this block's 2048 d's for all 26 classes -----
    // thread t -> global quad q = wg*512 + t (d = 4q..4q+3); valid iff q < 2500 (D/4).
    const int q      = wg * 512 + tid;
    const bool valid = (q < D / 4);
    const unsigned e  = s_enc[tid >> 3];    // local word = tid>>3
    const int bb      = (tid & 7) * 4;
    const unsigned MSB = 0x80000000u;
    const float4* cw4 = reinterpret_cast<const float4*>(cw);

    // sign masks precomputed once (independent of c)
    unsigned sm0 = (~(e << (31 - bb - 0))) & MSB;
    unsigned sm1 = (~(e << (31 - bb - 1))) & MSB;
    unsigned sm2 = (~(e << (31 - bb - 2))) & MSB;
    unsigned sm3 = (~(e << (31 - bb - 3))) & MSB;

    #pragma unroll
    for (int cb0 = 0; cb0 < C; cb0 += 13) {             // 2 batches of 13 classes
        float4 cv[13];
        #pragma unroll
        for (int i = 0; i < 13; i++)
            cv[i] = valid ? __ldg(cw4 + (size_t)(cb0 + i) * (D / 4) + q)
                          : make_float4(0.f, 0.f, 0.f, 0.f);
        #pragma unroll
        for (int i = 0; i < 13; i++) {
            float p = __uint_as_float(__float_as_uint(cv[i].x) ^ sm0)
                    + __uint_as_float(__float_as_uint(cv[i].y) ^ sm1)
                    + __uint_as_float(__float_as_uint(cv[i].z) ^ sm2)
                    + __uint_as_float(__float_as_uint(cv[i].w) ^ sm3);
            #pragma unroll
            for (int o = 16; o > 0; o >>= 1) p += __shfl_down_sync(0xffffffffu, p, o);
            if (lane == 0) sp[sg][cb0 + i] = p;
        }
        __syncthreads();
        if (tid < 13) {
            float s = 0.0f;
            #pragma unroll
            for (int k = 0; k < 16; k++) s += sp[k][cb0 + tid];
            atomicAdd(&out[b * C + cb0 + tid], s);
        }
        __syncthreads();
    }
}

// ================= launch =======================================================================
extern "C" void kernel_launch(void* const* d_in, const int* in_sizes, int n_in,
                              void* d_out, int out_size) {
    (void)in_sizes; (void)n_in; (void)out_size;
    const float* x   = (const float*)d_in[0];
    const float* idw = (const float*)d_in[1];
    const float* lvw = (const float*)d_in[2];
    const float* cw  = (const float*)d_in[3];
    float* out = (float*)d_out;

    prep_kernel<<<PREP_BLOCKS, 256>>>(idw, lvw, out);
    mainlogits_kernel<<<dim3(B, 5), 512>>>(x, cw, out);
}

// round 16
// speedup vs baseline: 1.1544x; 1.1544x over previous
#include <cuda_runtime.h>

#define B  32
#define S  617
#define D  10000
#define L  100
#define C  26
#define W  313        // ceil(D/32) real words
#define WP 320        // padded word count

// ---------------- scratch (device globals; pads stay zero forever) ------------------------------
__device__ __align__(16) int      g_idx[B * S];
__device__ __align__(16) unsigned g_idp[S * WP];   // packed id signs    [s][w]
__device__ __align__(16) unsigned g_lvp[L * WP];   // packed level signs [l][w]
__device__ __align__(16) unsigned g_enc[B * WP];   // packed enc (1 -> +1, 0 -> -1)

// ================= kernel 1: pack sign bits; wide grid, MLP-8 float4 + shfl (R8 verbatim) =======
#define NROWS (S + L)                        // 717
#define RPR   10                             // regions of 1024 floats per row
#define PREP_WARPS  (NROWS * RPR)            // 7170
#define PREP_XWARPS 617                      // B*S/32
#define PREP_BLOCKS ((PREP_WARPS + PREP_XWARPS + 7) / 8)   // 974

__global__ __launch_bounds__(256) void prep_kernel(const float* __restrict__ x,
                                                   const float* __restrict__ idw,
                                                   const float* __restrict__ lvw) {
    const int lane = threadIdx.x & 31;
    const int gw   = blockIdx.x * 8 + (threadIdx.x >> 5);

    if (gw < PREP_WARPS) {
        const int r      = gw / RPR;
        const int region = gw - r * RPR;
        const float* src = (r < S) ? (idw + (size_t)r * D) : (lvw + (size_t)(r - S) * D);
        unsigned*    dst = (r < S) ? (g_idp + r * WP)       : (g_lvp + (r - S) * WP);

        const int qbase = region * 256;

        float4 v[8];
        #pragma unroll
        for (int k = 0; k < 8; k++) {
            int q = qbase + k * 32 + lane;
            if (q < D / 4) v[k] = *reinterpret_cast<const float4*>(src + 4 * q);
            else           v[k] = make_float4(0.f, 0.f, 0.f, 0.f);
        }

        unsigned nib[8];
        #pragma unroll
        for (int k = 0; k < 8; k++) {
            unsigned n = (v[k].x > 0.f ? 1u : 0u) | (v[k].y > 0.f ? 2u : 0u)
                       | (v[k].z > 0.f ? 4u : 0u) | (v[k].w > 0.f ? 8u : 0u);
            n |= __shfl_down_sync(0xffffffffu, n, 1) << 4;
            n |= __shfl_down_sync(0xffffffffu, n, 2) << 8;
            n |= __shfl_down_sync(0xffffffffu, n, 4) << 16;
            nib[k] = n;
        }

        if ((lane & 7) == 0) {
            const int g = lane >> 3;
            #pragma unroll
            for (int k = 0; k < 8; k++) {
                int w = region * 32 + 4 * k + g;
                if (w < W) dst[w] = nib[k];
            }
        }
    } else {
        int e = (gw - PREP_WARPS) * 32 + lane;          // B*S = 19744 = 617*32 exactly
        if (e < B * S) {
            int qv = (int)rintf(x[e] * (float)(L - 1)); // round-half-even == jnp.round
            g_idx[e] = min(max(qv, 0), L - 1);
        }
    }
}

// ================= 6-sample bitplane compressor (26 LOP3 per 6 samples) =========================
__device__ __forceinline__ void csa6(const unsigned xx[6], unsigned p[7]) {
    unsigned t01 = xx[0] ^ xx[1];
    unsigned l1  = t01 ^ xx[2];
    unsigned h1  = (xx[0] & xx[1]) | (xx[2] & t01);
    unsigned t34 = xx[3] ^ xx[4];
    unsigned l2  = t34 ^ xx[5];
    unsigned h2  = (xx[3] & xx[4]) | (xx[5] & t34);
    unsigned tl = l1 ^ l2;
    unsigned c0 = (l1 & l2) | (p[0] & tl);
    p[0] ^= tl;
    unsigned th  = h1 ^ h2;
    unsigned c1a = (h1 & h2) | (p[1] & th);
    unsigned s1  = p[1] ^ th;
    unsigned c1b = s1 & c0;
    p[1] = s1 ^ c0;
    unsigned tc = c1a ^ c1b;
    unsigned c2 = (c1a & c1b) | (p[2] & tc);
    p[2] ^= tc;
    unsigned t;
    t = p[3] & c2; p[3] ^= c2; c2 = t;
    t = p[4] & c2; p[4] ^= c2; c2 = t;
    t = p[5] & c2; p[5] ^= c2; c2 = t;
    p[6] ^= c2;
}

// ================= bit-sliced compare cnt < 309 (309 = 0b0100110101) ===========================
__device__ __forceinline__ unsigned cmp309(const unsigned A[10]) {
    unsigned lt = 0u, eq = 0xffffffffu;
    eq &= ~A[9];
    lt |= eq & ~A[8]; eq &= A[8];
    eq &= ~A[7];
    eq &= ~A[6];
    lt |= eq & ~A[5]; eq &= A[5];
    lt |= eq & ~A[4]; eq &= A[4];
    eq &= ~A[3];
    lt |= eq & ~A[2]; eq &= A[2];
    eq &= ~A[1];
    lt |= eq & ~A[0];
    return lt;
}

// ================= kernel 2: R8 main + smem-staged level slice (lvp L2 traffic 25 MB -> 4 MB) ===
// grid (B, 5), 320 threads = 10 sample-group warps; thread owns 2 words (uint2).
__global__ __launch_bounds__(320) void main_kernel() {
    const int b    = blockIdx.x;
    const int wg   = blockIdx.y;            // 0..4, 64-word group
    const int sg   = threadIdx.x >> 5;      // 0..9 sample group
    const int lane = threadIdx.x & 31;
    const int tid  = threadIdx.x;
    const int w0   = wg * 64 + lane * 2;    // even global word index
    const int lw0  = lane * 2;              // local word index within 64

    __shared__ __align__(16) unsigned pl[10 * 7 * 64];  // 17.9 KB
    __shared__ __align__(16) unsigned lvq[L * 64];      // level slice [l][64 words] 25.6 KB
    __shared__ __align__(16) int      sidx[624];        // 2.5 KB

    // stage level slice: 6400 words, coalesced uint2 loads (row stride WP -> dense 64)
    for (int i = tid; i < L * 32; i += 320) {
        int l  = i >> 5;                     // level
        int p2 = i & 31;                     // uint2 pair within row
        *reinterpret_cast<uint2*>(&lvq[l * 64 + p2 * 2]) =
            *reinterpret_cast<const uint2*>(g_lvp + l * WP + wg * 64 + p2 * 2);
    }
    for (int s = tid; s < S; s += 320) sidx[s] = g_idx[b * S + s];
    __syncthreads();

    const int s0 = sg * 62;
    const int sn = (sg == 9) ? 59 : 62;     // 9*62 + 59 = 617

    unsigned pA[7] = {0,0,0,0,0,0,0};
    unsigned pB[7] = {0,0,0,0,0,0,0};

    const int full6 = sn / 6;               // 10 or 9
    for (int g = 0; g < full6; g++) {
        unsigned xa[6], xb[6];
        #pragma unroll
        for (int k = 0; k < 6; k++) {
            int s = s0 + g * 6 + k;
            uint2 a = *reinterpret_cast<const uint2*>(g_idp + s * WP + w0);
            uint2 l = *reinterpret_cast<const uint2*>(&lvq[sidx[s] * 64 + lw0]);
            xa[k] = a.x ^ l.x;
            xb[k] = a.y ^ l.y;
        }
        csa6(xa, pA);
        csa6(xb, pB);
    }
    for (int s = s0 + full6 * 6; s < s0 + sn; s++) {     // remainder 2 or 5 samples
        uint2 a = *reinterpret_cast<const uint2*>(g_idp + s * WP + w0);
        uint2 l = *reinterpret_cast<const uint2*>(&lvq[sidx[s] * 64 + lw0]);
        unsigned cA = a.x ^ l.x, cB = a.y ^ l.y;
        #pragma unroll
        for (int k = 0; k < 7; k++) {
            unsigned t = pA[k] & cA; pA[k] ^= cA; cA = t;
            t = pB[k] & cB; pB[k] ^= cB; cB = t;
        }
    }

    #pragma unroll
    for (int k = 0; k < 7; k++) {
        uint2 v; v.x = pA[k]; v.y = pB[k];
        *reinterpret_cast<uint2*>(&pl[(sg * 7 + k) * 64 + lw0]) = v;
    }
    __syncthreads();

    if (tid < 32) {
        unsigned A[10], Bv[10];
        #pragma unroll
        for (int k = 0; k < 10; k++) { A[k] = 0u; Bv[k] = 0u; }
        #pragma unroll
        for (int g2 = 0; g2 < 10; g2++) {
            unsigned cA = 0u, cB = 0u;
            #pragma unroll
            for (int k = 0; k < 7; k++) {
                uint2 q = *reinterpret_cast<const uint2*>(&pl[(g2 * 7 + k) * 64 + lane * 2]);
                unsigned sA = A[k] ^ q.x ^ cA;
                cA = (A[k] & q.x) | (cA & (A[k] ^ q.x));
                A[k] = sA;
                unsigned sB = Bv[k] ^ q.y ^ cB;
                cB = (Bv[k] & q.y) | (cB & (Bv[k] ^ q.y));
                Bv[k] = sB;
            }
            #pragma unroll
            for (int k = 7; k < 10; k++) {
                unsigned t = A[k] & cA;  A[k] ^= cA;  cA = t;
                t = Bv[k] & cB; Bv[k] ^= cB; cB = t;
            }
        }
        uint2 v; v.x = cmp309(A); v.y = cmp309(Bv);
        *reinterpret_cast<uint2*>(g_enc + b * WP + wg * 64 + lane * 2) = v;
    }
}

// ================= kernel 3: logits (R8 verbatim) ===============================================
__global__ __launch_bounds__(320) void logits_kernel(const float* __restrict__ cw,
                                                     float* __restrict__ out) {
    const int c    = blockIdx.x;
    const int b0   = blockIdx.y * 4;
    const int tid  = threadIdx.x;
    const int lane = tid & 31;
    const int wrp  = tid >> 5;
    const int bb   = (tid & 7) * 4;         // bit base within word

    __shared__ __align__(16) uint4 se4[WP];
    __shared__ float red[10][4];
    {
        uint4 v;
        v.x = g_enc[(b0 + 0) * WP + tid];
        v.y = g_enc[(b0 + 1) * WP + tid];
        v.z = g_enc[(b0 + 2) * WP + tid];
        v.w = g_enc[(b0 + 3) * WP + tid];
        se4[tid] = v;
    }
    __syncthreads();

    const float4* cw4 = reinterpret_cast<const float4*>(cw + (size_t)c * D);
    const unsigned MSB = 0x80000000u;

    float4 cv[7];
    uint4  ev[7];
    #pragma unroll
    for (int k = 0; k < 7; k++) cv[k] = __ldg(cw4 + k * 320 + tid);
    #pragma unroll
    for (int k = 0; k < 7; k++) ev[k] = se4[k * 40 + (tid >> 3)];

    float a0 = 0.f, a1 = 0.f, a2 = 0.f, a3 = 0.f;

    #pragma unroll
    for (int k = 0; k < 7; k++) {
        const float* cf = &cv[k].x;
        #pragma unroll
        for (int j = 0; j < 4; j++) {
            unsigned cb = __float_as_uint(cf[j]);
            int sh = 31 - bb - j;
            a0 += __uint_as_float(cb ^ (~(ev[k].x << sh) & MSB));
            a1 += __uint_as_float(cb ^ (~(ev[k].y << sh) & MSB));
            a2 += __uint_as_float(cb ^ (~(ev[k].z << sh) & MSB));
            a3 += __uint_as_float(cb ^ (~(ev[k].w << sh) & MSB));
        }
    }
    if (tid < 260) {                         // tail quads 2240..2499
        float4 cv7 = __ldg(cw4 + 2240 + tid);
        uint4  ev7 = se4[280 + (tid >> 3)];
        const float* cf = &cv7.x;
        #pragma unroll
        for (int j = 0; j < 4; j++) {
            unsigned cb = __float_as_uint(cf[j]);
            int sh = 31 - bb - j;
            a0 += __uint_as_float(cb ^ (~(ev7.x << sh) & MSB));
            a1 += __uint_as_float(cb ^ (~(ev7.y << sh) & MSB));
            a2 += __uint_as_float(cb ^ (~(ev7.z << sh) & MSB));
            a3 += __uint_as_float(cb ^ (~(ev7.w << sh) & MSB));
        }
    }

    float a[4] = {a0, a1, a2, a3};
    #pragma unroll
    for (int i = 0; i < 4; i++) {
        float s = a[i];
        #pragma unroll
        for (int o = 16; o > 0; o >>= 1) s += __shfl_down_sync(0xffffffffu, s, o);
        if (lane == 0) red[wrp][i] = s;
    }
    __syncthreads();
    if (tid < 4) {
        float s = 0.0f;
        #pragma unroll
        for (int k = 0; k < 10; k++) s += red[k][tid];
        out[(b0 + tid) * C + c] = s;
    }
}

// ================= launch =======================================================================
extern "C" void kernel_launch(void* const* d_in, const int* in_sizes, int n_in,
                              void* d_out, int out_size) {
    (void)in_sizes; (void)n_in; (void)out_size;
    const float* x   = (const float*)d_in[0];
    const float* idw = (const float*)d_in[1];
    const float* lvw = (const float*)d_in[2];
    const float* cw  = (const float*)d_in[3];
    float* out = (float*)d_out;

    prep_kernel<<<PREP_BLOCKS, 256>>>(x, idw, lvw);
    main_kernel<<<dim3(B, 5), 320>>>();
    logits_kernel<<<dim3(C, B / 4), 320>>>(cw, out);
}

// round 17
// speedup vs baseline: 1.3103x; 1.1351x over previous
#include <cuda_runtime.h>

#define B  32
#define S  617
#define D  10000
#define L  100
#define C  26
#define W  313        // ceil(D/32) real words
#define WP 320        // padded word count

// ---------------- scratch (device globals; pads stay zero forever) ------------------------------
__device__ __align__(16) unsigned g_idp[S * WP];   // packed id signs    [s][w]
__device__ __align__(16) unsigned g_lvp[L * WP];   // packed level signs [l][w]
__device__ __align__(16) unsigned g_enc[B * WP];   // packed enc (1 -> +1, 0 -> -1)

// ================= kernel 1: pack sign bits; wide grid, MLP-8 float4 + shfl, streaming loads ====
#define NROWS (S + L)                        // 717
#define RPR   10                             // regions of 1024 floats per row
#define PREP_WARPS  (NROWS * RPR)            // 7170
#define PREP_BLOCKS ((PREP_WARPS + 7) / 8)   // 897

__global__ __launch_bounds__(256) void prep_kernel(const float* __restrict__ idw,
                                                   const float* __restrict__ lvw) {
    const int lane = threadIdx.x & 31;
    const int gw   = blockIdx.x * 8 + (threadIdx.x >> 5);
    if (gw >= PREP_WARPS) return;

    const int r      = gw / RPR;
    const int region = gw - r * RPR;
    const float* src = (r < S) ? (idw + (size_t)r * D) : (lvw + (size_t)(r - S) * D);
    unsigned*    dst = (r < S) ? (g_idp + r * WP)       : (g_lvp + (r - S) * WP);

    const int qbase = region * 256;

    // 8 independent coalesced LDG.128, streaming (single-use data), front-batched
    float4 v[8];
    #pragma unroll
    for (int k = 0; k < 8; k++) {
        int q = qbase + k * 32 + lane;
        v[k] = (q < D / 4) ? __ldcs(reinterpret_cast<const float4*>(src) + q)
                           : make_float4(0.f, 0.f, 0.f, 0.f);
    }

    unsigned nib[8];
    #pragma unroll
    for (int k = 0; k < 8; k++) {
        unsigned n = (v[k].x > 0.f ? 1u : 0u) | (v[k].y > 0.f ? 2u : 0u)
                   | (v[k].z > 0.f ? 4u : 0u) | (v[k].w > 0.f ? 8u : 0u);
        n |= __shfl_down_sync(0xffffffffu, n, 1) << 4;
        n |= __shfl_down_sync(0xffffffffu, n, 2) << 8;
        n |= __shfl_down_sync(0xffffffffu, n, 4) << 16;
        nib[k] = n;
    }

    if ((lane & 7) == 0) {
        const int g = lane >> 3;
        #pragma unroll
        for (int k = 0; k < 8; k++) {
            int w = region * 32 + 4 * k + g;
            if (w < W) dst[w] = nib[k];
        }
    }
}

// ================= 6-sample bitplane compressor (26 LOP3 per 6 samples) =========================
__device__ __forceinline__ void csa6(const unsigned xx[6], unsigned p[7]) {
    unsigned t01 = xx[0] ^ xx[1];
    unsigned l1  = t01 ^ xx[2];
    unsigned h1  = (xx[0] & xx[1]) | (xx[2] & t01);
    unsigned t34 = xx[3] ^ xx[4];
    unsigned l2  = t34 ^ xx[5];
    unsigned h2  = (xx[3] & xx[4]) | (xx[5] & t34);
    unsigned tl = l1 ^ l2;
    unsigned c0 = (l1 & l2) | (p[0] & tl);
    p[0] ^= tl;
    unsigned th  = h1 ^ h2;
    unsigned c1a = (h1 & h2) | (p[1] & th);
    unsigned s1  = p[1] ^ th;
    unsigned c1b = s1 & c0;
    p[1] = s1 ^ c0;
    unsigned tc = c1a ^ c1b;
    unsigned c2 = (c1a & c1b) | (p[2] & tc);
    p[2] ^= tc;
    unsigned t;
    t = p[3] & c2; p[3] ^= c2; c2 = t;
    t = p[4] & c2; p[4] ^= c2; c2 = t;
    t = p[5] & c2; p[5] ^= c2; c2 = t;
    p[6] ^= c2;
}

// ================= bit-sliced compare cnt < 309 (309 = 0b0100110101) ===========================
__device__ __forceinline__ unsigned cmp309(const unsigned A[10]) {
    unsigned lt = 0u, eq = 0xffffffffu;
    eq &= ~A[9];
    lt |= eq & ~A[8]; eq &= A[8];
    eq &= ~A[7];
    eq &= ~A[6];
    lt |= eq & ~A[5]; eq &= A[5];
    lt |= eq & ~A[4]; eq &= A[4];
    eq &= ~A[3];
    lt |= eq & ~A[2]; eq &= A[2];
    eq &= ~A[1];
    lt |= eq & ~A[0];
    return lt;
}

// ================= kernel 2: bind + count + merge -> g_enc (R8 geometry, inline x-quantize) =====
// grid (B, 5), 320 threads = 10 sample-group warps; each thread owns 2 words (uint2).
__global__ __launch_bounds__(320) void main_kernel(const float* __restrict__ x) {
    const int b    = blockIdx.x;
    const int wg   = blockIdx.y;            // 0..4, 64-word group
    const int sg   = threadIdx.x >> 5;      // 0..9 sample group
    const int lane = threadIdx.x & 31;
    const int w0   = wg * 64 + lane * 2;    // even word index

    __shared__ __align__(16) unsigned pl[10 * 7 * 64];  // [sg][plane][64 words]
    __shared__ __align__(16) int      sidx[624];         // padded S

    // quantize x row b inline (rintf = round-half-even, matches jnp.round)
    for (int i = threadIdx.x; i < S; i += 320) {
        int qv = (int)rintf(__ldg(&x[b * S + i]) * (float)(L - 1));
        sidx[i] = min(max(qv, 0), L - 1);
    }
    __syncthreads();

    const int s0 = sg * 62;
    const int sn = (sg == 9) ? 59 : 62;     // 9*62 + 59 = 617

    unsigned pA[7] = {0,0,0,0,0,0,0};
    unsigned pB[7] = {0,0,0,0,0,0,0};

    const int full6 = sn / 6;               // 10 or 9
    for (int g = 0; g < full6; g++) {
        unsigned xa[6], xb[6];
        #pragma unroll
        for (int k = 0; k < 6; k++) {
            int s = s0 + g * 6 + k;
            uint2 a = *reinterpret_cast<const uint2*>(g_idp + s * WP + w0);
            uint2 l = *reinterpret_cast<const uint2*>(g_lvp + sidx[s] * WP + w0);
            xa[k] = a.x ^ l.x;
            xb[k] = a.y ^ l.y;
        }
        csa6(xa, pA);
        csa6(xb, pB);
    }
    for (int s = s0 + full6 * 6; s < s0 + sn; s++) {   // remainder 2 or 5 samples
        uint2 a = *reinterpret_cast<const uint2*>(g_idp + s * WP + w0);
        uint2 l = *reinterpret_cast<const uint2*>(g_lvp + sidx[s] * WP + w0);
        unsigned cA = a.x ^ l.x, cB = a.y ^ l.y;
        #pragma unroll
        for (int k = 0; k < 7; k++) {
            unsigned t = pA[k] & cA; pA[k] ^= cA; cA = t;
            t = pB[k] & cB; pB[k] ^= cB; cB = t;
        }
    }

    #pragma unroll
    for (int k = 0; k < 7; k++) {
        uint2 v; v.x = pA[k]; v.y = pB[k];
        *reinterpret_cast<uint2*>(&pl[(sg * 7 + k) * 64 + lane * 2]) = v;
    }
    __syncthreads();

    if (threadIdx.x < 32) {
        unsigned A[10], Bv[10];
        #pragma unroll
        for (int k = 0; k < 10; k++) { A[k] = 0u; Bv[k] = 0u; }
        #pragma unroll
        for (int g2 = 0; g2 < 10; g2++) {
            unsigned cA = 0u, cB = 0u;
            #pragma unroll
            for (int k = 0; k < 7; k++) {
                uint2 q = *reinterpret_cast<const uint2*>(&pl[(g2 * 7 + k) * 64 + lane * 2]);
                unsigned sA = A[k] ^ q.x ^ cA;
                cA = (A[k] & q.x) | (cA & (A[k] ^ q.x));
                A[k] = sA;
                unsigned sB = Bv[k] ^ q.y ^ cB;
                cB = (Bv[k] & q.y) | (cB & (Bv[k] ^ q.y));
                Bv[k] = sB;
            }
            #pragma unroll
            for (int k = 7; k < 10; k++) {
                unsigned t = A[k] & cA;  A[k] ^= cA;  cA = t;
                t = Bv[k] & cB; Bv[k] ^= cB; cB = t;
            }
        }
        uint2 v; v.x = cmp309(A); v.y = cmp309(Bv);
        *reinterpret_cast<uint2*>(g_enc + b * WP + w0) = v;
    }
}

// ================= kernel 3: logits, float4 cw + front-batched loads (R8 verbatim) ==============
__global__ __launch_bounds__(320) void logits_kernel(const float* __restrict__ cw,
                                                     float* __restrict__ out) {
    const int c    = blockIdx.x;
    const int b0   = blockIdx.y * 4;
    const int tid  = threadIdx.x;
    const int lane = tid & 31;
    const int wrp  = tid >> 5;
    const int bb   = (tid & 7) * 4;         // bit base within word

    __shared__ __align__(16) uint4 se4[WP];
    __shared__ float red[10][4];
    {
        uint4 v;
        v.x = g_enc[(b0 + 0) * WP + tid];
        v.y = g_enc[(b0 + 1) * WP + tid];
        v.z = g_enc[(b0 + 2) * WP + tid];
        v.w = g_enc[(b0 + 3) * WP + tid];
        se4[tid] = v;
    }
    __syncthreads();

    const float4* cw4 = reinterpret_cast<const float4*>(cw + (size_t)c * D);
    const unsigned MSB = 0x80000000u;

    float4 cv[7];
    uint4  ev[7];
    #pragma unroll
    for (int k = 0; k < 7; k++) cv[k] = __ldg(cw4 + k * 320 + tid);
    #pragma unroll
    for (int k = 0; k < 7; k++) ev[k] = se4[k * 40 + (tid >> 3)];

    float a0 = 0.f, a1 = 0.f, a2 = 0.f, a3 = 0.f;

    #pragma unroll
    for (int k = 0; k < 7; k++) {
        const float* cf = &cv[k].x;
        #pragma unroll
        for (int j = 0; j < 4; j++) {
            unsigned cb = __float_as_uint(cf[j]);
            int sh = 31 - bb - j;
            a0 += __uint_as_float(cb ^ (~(ev[k].x << sh) & MSB));
            a1 += __uint_as_float(cb ^ (~(ev[k].y << sh) & MSB));
            a2 += __uint_as_float(cb ^ (~(ev[k].z << sh) & MSB));
            a3 += __uint_as_float(cb ^ (~(ev[k].w << sh) & MSB));
        }
    }
    if (tid < 260) {                         // tail quads 2240..2499
        float4 cv7 = __ldg(cw4 + 2240 + tid);
        uint4  ev7 = se4[280 + (tid >> 3)];
        const float* cf = &cv7.x;
        #pragma unroll
        for (int j = 0; j < 4; j++) {
            unsigned cb = __float_as_uint(cf[j]);
            int sh = 31 - bb - j;
            a0 += __uint_as_float(cb ^ (~(ev7.x << sh) & MSB));
            a1 += __uint_as_float(cb ^ (~(ev7.y << sh) & MSB));
            a2 += __uint_as_float(cb ^ (~(ev7.z << sh) & MSB));
            a3 += __uint_as_float(cb ^ (~(ev7.w << sh) & MSB));
        }
    }

    float a[4] = {a0, a1, a2, a3};
    #pragma unroll
    for (int i = 0; i < 4; i++) {
        float s = a[i];
        #pragma unroll
        for (int o = 16; o > 0; o >>= 1) s += __shfl_down_sync(0xffffffffu, s, o);
        if (lane == 0) red[wrp][i] = s;
    }
    __syncthreads();
    if (tid < 4) {
        float s = 0.0f;
        #pragma unroll
        for (int k = 0; k < 10; k++) s += red[k][tid];
        out[(b0 + tid) * C + c] = s;
    }
}

// ================= launch =======================================================================
extern "C" void kernel_launch(void* const* d_in, const int* in_sizes, int n_in,
                              void* d_out, int out_size) {
    (void)in_sizes; (void)n_in; (void)out_size;
    const float* x   = (const float*)d_in[0];
    const float* idw = (const float*)d_in[1];
    const float* lvw = (const float*)d_in[2];
    const float* cw  = (const float*)d_in[3];
    float* out = (float*)d_out;

    prep_kernel<<<PREP_BLOCKS, 256>>>(idw, lvw);
    main_kernel<<<dim3(B, 5), 320>>>(x);
    logits_kernel<<<dim3(C, B / 4), 320>>>(cw, out);
}